// round 1
// baseline (speedup 1.0000x reference)
#include <cuda_runtime.h>
#include <math.h>

#define NROWS 8192
#define CH    512
#define NC    (NROWS * CH)          // 4,194,304 elements per [N, 512] matrix

// Scratch layout (one big device-global array, ~400 MB):
// [0]: q, [1]: k1, [2]: k2, [3]: v, [4]: a1, [5]: a2, [6]: gate,
// [7]: attn1, [8]: attn2, then S (8192*8192)
__device__ float g_scratch[(size_t)9 * NC + (size_t)NROWS * NROWS];

// ---------------------------------------------------------------------------
// Tiled SGEMM: C[M,N] = scale * (A @ op(B)) + bias
//   TRANSB=true : B is [N,K] row-major (weights), op(B) = B^T
//   TRANSB=false: B is [K,N] row-major, op(B) = B
// A may be a K-concat of up to 3 sources, each [M,512] row-major (A1 != null
// signals concat mode; every 512-chunk of K comes from A0/A1/A2).
// Block tile 128x128, K-tile 16, 256 threads, 8x8 per-thread microtile.
// All problem dims here are multiples of the tiles -> no bounds checks.
// ---------------------------------------------------------------------------
template <bool TRANSB>
__global__ void __launch_bounds__(256, 2)
sgemm_kernel(float* __restrict__ C,
             const float* __restrict__ A0,
             const float* __restrict__ A1,
             const float* __restrict__ A2,
             const float* __restrict__ B,
             const float* __restrict__ bias,
             int M, int N, int K, float scale)
{
    __shared__ float As[16][132];   // +4 pad keeps 16B alignment, cuts conflicts
    __shared__ float Bs[16][132];

    const int tid = threadIdx.x;
    const int tx  = tid & 15;
    const int ty  = tid >> 4;
    const int m0  = blockIdx.y * 128;
    const int n0  = blockIdx.x * 128;

    // Loader mapping (512 float4 per tile, 2 per thread)
    const int a_row = tid >> 2;     // 0..63
    const int a_cv  = tid & 3;      // float4 column within 16-wide K tile
    const int b_kr  = tid >> 5;     // 0..7   (TRANSB=false path)
    const int b_nv  = tid & 31;     // 0..31  (TRANSB=false path)

    float acc[8][8];
#pragma unroll
    for (int i = 0; i < 8; i++)
#pragma unroll
        for (int j = 0; j < 8; j++) acc[i][j] = 0.0f;

    float4 pa0, pa1, pb0, pb1;

    auto loadA = [&](int k0) {
        const float* src;
        int lda, col0;
        if (A1 != nullptr) {        // concat mode: K split into 512-chunks
            int seg = k0 >> 9;
            src  = (seg == 0) ? A0 : ((seg == 1) ? A1 : A2);
            col0 = k0 & 511;
            lda  = 512;
        } else {
            src  = A0; col0 = k0; lda = K;
        }
        pa0 = *(const float4*)(src + (size_t)(m0 + a_row)      * lda + col0 + a_cv * 4);
        pa1 = *(const float4*)(src + (size_t)(m0 + a_row + 64) * lda + col0 + a_cv * 4);
    };
    auto loadB = [&](int k0) {
        if (TRANSB) {
            pb0 = *(const float4*)(B + (size_t)(n0 + a_row)      * K + k0 + a_cv * 4);
            pb1 = *(const float4*)(B + (size_t)(n0 + a_row + 64) * K + k0 + a_cv * 4);
        } else {
            pb0 = *(const float4*)(B + (size_t)(k0 + b_kr)     * N + n0 + b_nv * 4);
            pb1 = *(const float4*)(B + (size_t)(k0 + b_kr + 8) * N + n0 + b_nv * 4);
        }
    };
    auto storeAB = [&]() {
        const float* f0 = (const float*)&pa0;
        const float* f1 = (const float*)&pa1;
#pragma unroll
        for (int j = 0; j < 4; j++) {
            As[a_cv * 4 + j][a_row]      = f0[j];
            As[a_cv * 4 + j][a_row + 64] = f1[j];
        }
        if (TRANSB) {
            const float* g0 = (const float*)&pb0;
            const float* g1 = (const float*)&pb1;
#pragma unroll
            for (int j = 0; j < 4; j++) {
                Bs[a_cv * 4 + j][a_row]      = g0[j];
                Bs[a_cv * 4 + j][a_row + 64] = g1[j];
            }
        } else {
            *(float4*)&Bs[b_kr][b_nv * 4]     = pb0;
            *(float4*)&Bs[b_kr + 8][b_nv * 4] = pb1;
        }
    };

    loadA(0); loadB(0);
    storeAB();
    __syncthreads();

    for (int k0 = 0; k0 < K; k0 += 16) {
        const bool last = (k0 + 16 >= K);
        if (!last) { loadA(k0 + 16); loadB(k0 + 16); }

#pragma unroll
        for (int kk = 0; kk < 16; kk++) {
            float4 av0 = *(const float4*)&As[kk][ty * 4];
            float4 av1 = *(const float4*)&As[kk][64 + ty * 4];
            float4 bv0 = *(const float4*)&Bs[kk][tx * 4];
            float4 bv1 = *(const float4*)&Bs[kk][64 + tx * 4];
            float af[8] = {av0.x, av0.y, av0.z, av0.w, av1.x, av1.y, av1.z, av1.w};
            float bf[8] = {bv0.x, bv0.y, bv0.z, bv0.w, bv1.x, bv1.y, bv1.z, bv1.w};
#pragma unroll
            for (int i = 0; i < 8; i++)
#pragma unroll
                for (int j = 0; j < 8; j++)
                    acc[i][j] = fmaf(af[i], bf[j], acc[i][j]);
        }
        __syncthreads();
        if (!last) { storeAB(); __syncthreads(); }
    }

    // Epilogue
#pragma unroll
    for (int i = 0; i < 8; i++) {
        const int r = (i < 4) ? (ty * 4 + i) : (64 + ty * 4 + (i - 4));
        float* crow = C + (size_t)(m0 + r) * N + n0;
#pragma unroll
        for (int half = 0; half < 2; half++) {
            const int c = (half == 0) ? (tx * 4) : (64 + tx * 4);
            float4 o;
            o.x = acc[i][half * 4 + 0] * scale;
            o.y = acc[i][half * 4 + 1] * scale;
            o.z = acc[i][half * 4 + 2] * scale;
            o.w = acc[i][half * 4 + 3] * scale;
            if (bias != nullptr) {
                o.x += bias[n0 + c + 0];
                o.y += bias[n0 + c + 1];
                o.z += bias[n0 + c + 2];
                o.w += bias[n0 + c + 3];
            }
            *(float4*)(crow + c) = o;
        }
    }
}

// ---------------------------------------------------------------------------
// Row softmax over 8192 columns. One block (256 threads) per row; whole row
// lives in registers (8 float4 per thread).
// ---------------------------------------------------------------------------
__global__ void __launch_bounds__(256)
softmax_kernel(float* __restrict__ S)
{
    const int tid = threadIdx.x;
    float* p = S + (size_t)blockIdx.x * 8192;

    __shared__ float red1[8];
    __shared__ float red2[8];

    float4 v[8];
#pragma unroll
    for (int i = 0; i < 8; i++)
        v[i] = *(const float4*)(p + (size_t)(i * 256 + tid) * 4);

    // --- max ---
    float m = -3.0e38f;
#pragma unroll
    for (int i = 0; i < 8; i++) {
        m = fmaxf(m, fmaxf(fmaxf(v[i].x, v[i].y), fmaxf(v[i].z, v[i].w)));
    }
#pragma unroll
    for (int o = 16; o > 0; o >>= 1)
        m = fmaxf(m, __shfl_xor_sync(0xffffffff, m, o));
    if ((tid & 31) == 0) red1[tid >> 5] = m;
    __syncthreads();
    m = red1[0];
#pragma unroll
    for (int i = 1; i < 8; i++) m = fmaxf(m, red1[i]);

    // --- exp + sum ---
    float s = 0.0f;
#pragma unroll
    for (int i = 0; i < 8; i++) {
        v[i].x = __expf(v[i].x - m); s += v[i].x;
        v[i].y = __expf(v[i].y - m); s += v[i].y;
        v[i].z = __expf(v[i].z - m); s += v[i].z;
        v[i].w = __expf(v[i].w - m); s += v[i].w;
    }
#pragma unroll
    for (int o = 16; o > 0; o >>= 1)
        s += __shfl_xor_sync(0xffffffff, s, o);
    if ((tid & 31) == 0) red2[tid >> 5] = s;
    __syncthreads();
    s = 0.0f;
#pragma unroll
    for (int i = 0; i < 8; i++) s += red2[i];
    const float inv = 1.0f / s;

#pragma unroll
    for (int i = 0; i < 8; i++) {
        v[i].x *= inv; v[i].y *= inv; v[i].z *= inv; v[i].w *= inv;
        *(float4*)(p + (size_t)(i * 256 + tid) * 4) = v[i];
    }
}

// gate = sigmoid(sigmoid(a1) - sigmoid(a2))
// (softmax over a stacked pair of sigmoids == sigmoid of their difference)
__global__ void __launch_bounds__(256)
gate_kernel(float* __restrict__ g, const float* __restrict__ a1,
            const float* __restrict__ a2, int n)
{
    int i = blockIdx.x * 256 + threadIdx.x;
    if (i < n) {
        float s1 = 1.0f / (1.0f + __expf(-a1[i]));
        float s2 = 1.0f / (1.0f + __expf(-a2[i]));
        g[i] = 1.0f / (1.0f + __expf(-(s1 - s2)));
    }
}

__global__ void __launch_bounds__(256)
combine_kernel(float* __restrict__ out, const float* __restrict__ g,
               const float* __restrict__ A1, const float* __restrict__ A2, int n)
{
    int i = blockIdx.x * 256 + threadIdx.x;
    if (i < n) {
        float gg = g[i];
        out[i] = gg * A1[i] + (1.0f - gg) * A2[i];
    }
}

// ---------------------------------------------------------------------------
extern "C" void kernel_launch(void* const* d_in, const int* in_sizes, int n_in,
                              void* d_out, int out_size)
{
    const float* sp   = (const float*)d_in[0];
    const float* om1  = (const float*)d_in[1];
    const float* om2  = (const float*)d_in[2];
    const float* q_w  = (const float*)d_in[3];
    const float* q_b  = (const float*)d_in[4];
    const float* k1_w = (const float*)d_in[5];
    const float* k1_b = (const float*)d_in[6];
    const float* k2_w = (const float*)d_in[7];
    const float* k2_b = (const float*)d_in[8];
    const float* v_w  = (const float*)d_in[9];
    const float* v_b  = (const float*)d_in[10];
    const float* c1_w = (const float*)d_in[11];
    const float* c1_b = (const float*)d_in[12];
    float* out = (float*)d_out;

    float* base = nullptr;
    cudaGetSymbolAddress((void**)&base, g_scratch);
    float* q     = base + (size_t)0 * NC;
    float* k1    = base + (size_t)1 * NC;
    float* k2    = base + (size_t)2 * NC;
    float* v     = base + (size_t)3 * NC;
    float* a1    = base + (size_t)4 * NC;
    float* a2    = base + (size_t)5 * NC;
    float* gate  = base + (size_t)6 * NC;
    float* attn1 = base + (size_t)7 * NC;
    float* attn2 = base + (size_t)8 * NC;
    float* S     = base + (size_t)9 * NC;

    const float scale = 0.044194173824159223f;   // 1/sqrt(512)
    const dim3 gridProj(CH / 128, NROWS / 128);      // (4, 64)
    const dim3 gridS(NROWS / 128, NROWS / 128);      // (64, 64)
    const int elemBlocks = (NC + 255) / 256;

    // Projections
    sgemm_kernel<true><<<gridProj, 256>>>(q,  sp,  nullptr, nullptr, q_w,  q_b,  NROWS, CH, 512, 1.0f);
    sgemm_kernel<true><<<gridProj, 256>>>(k1, om1, nullptr, nullptr, k1_w, k1_b, NROWS, CH, 512, 1.0f);
    sgemm_kernel<true><<<gridProj, 256>>>(k2, om2, nullptr, nullptr, k2_w, k2_b, NROWS, CH, 512, 1.0f);
    sgemm_kernel<true><<<gridProj, 256>>>(v,  sp,  om1, om2, v_w, v_b, NROWS, CH, 1536, 1.0f);

    // Gate logits + gate
    sgemm_kernel<true><<<gridProj, 256>>>(a1, sp, om1, nullptr, c1_w, c1_b, NROWS, CH, 1024, 1.0f);
    sgemm_kernel<true><<<gridProj, 256>>>(a2, sp, om2, nullptr, c1_w, c1_b, NROWS, CH, 1024, 1.0f);
    gate_kernel<<<elemBlocks, 256>>>(gate, a1, a2, NC);

    // Attention 1
    sgemm_kernel<true><<<gridS, 256>>>(S, q, nullptr, nullptr, k1, nullptr, NROWS, NROWS, 512, scale);
    softmax_kernel<<<NROWS, 256>>>(S);
    sgemm_kernel<false><<<gridProj, 256>>>(attn1, S, nullptr, nullptr, v, nullptr, NROWS, CH, NROWS, 1.0f);

    // Attention 2
    sgemm_kernel<true><<<gridS, 256>>>(S, q, nullptr, nullptr, k2, nullptr, NROWS, NROWS, 512, scale);
    softmax_kernel<<<NROWS, 256>>>(S);
    sgemm_kernel<false><<<gridProj, 256>>>(attn2, S, nullptr, nullptr, v, nullptr, NROWS, CH, NROWS, 1.0f);

    // Combine
    combine_kernel<<<elemBlocks, 256>>>(out, gate, attn1, attn2, NC);
}

// round 3
// speedup vs baseline: 1.9123x; 1.9123x over previous
#include <cuda_runtime.h>
#include <cstdint>

#define NROWS 8192
#define CH    512
#define NC    ((size_t)NROWS * CH)
#define S_ELEMS ((size_t)NROWS * NROWS)
#define W_ELEMS 2097152

// q,k1,k2,v,a1(->vT),a2,gate,attn1,attn2,spr,om1r,om2r, S, rounded weights
__device__ float g_scratch[12 * NC + S_ELEMS + W_ELEMS];

// ===========================================================================
// helpers
// ===========================================================================
__device__ __forceinline__ uint32_t smem_u32(const void* p) {
    uint32_t a;
    asm("{ .reg .u64 t; cvta.to.shared.u64 t, %1; cvt.u32.u64 %0, t; }"
        : "=r"(a) : "l"(p));
    return a;
}
__device__ __forceinline__ float tf32r(float x) {
    float y;
    asm("cvt.rna.tf32.f32 %0, %1;" : "=f"(y) : "f"(x));
    return y;
}
__device__ __forceinline__ void cp16(uint32_t dst, const float* src) {
    asm volatile("cp.async.cg.shared.global [%0], [%1], 16;" :: "r"(dst), "l"(src));
}
__device__ __forceinline__ void mma_tf32(float* d, const uint32_t* a, const uint32_t* b) {
    asm volatile(
        "mma.sync.aligned.m16n8k8.row.col.f32.tf32.tf32.f32 "
        "{%0,%1,%2,%3}, {%4,%5,%6,%7}, {%8,%9}, {%0,%1,%2,%3};"
        : "+f"(d[0]), "+f"(d[1]), "+f"(d[2]), "+f"(d[3])
        : "r"(a[0]), "r"(a[1]), "r"(a[2]), "r"(a[3]), "r"(b[0]), "r"(b[1]));
}

// ===========================================================================
// tf32 NT GEMM via mma.sync: C[M x Nfull], tile 128x128
//   A: K-major, optionally 3-segment K-concat (segment len = 1<<seg_shift)
//   B: [Nfull, K] row-major (i.e., op(B)=B^T)
// 256 threads = 8 warps (4 m x 2 n), per-warp 32x64, BK=32, 3-stage cp.async.
// ===========================================================================
#define BK          32
#define ROWPAD      36                      // floats per smem row
#define A_TILE_B    (128 * ROWPAD * 4)      // 18432 B
#define STAGE_B     (2 * A_TILE_B)          // 36864 B
#define STAGES      3
#define SMEM_GEMM   (STAGES * STAGE_B)      // 110592 B

__global__ void __launch_bounds__(256, 1)
mma_nt_kernel(float* __restrict__ C,
              const float* __restrict__ A0, const float* __restrict__ A1,
              const float* __restrict__ A2,
              const float* __restrict__ B, const float* __restrict__ bias,
              int Nfull, int K, int seg_shift, float scale, int round_out)
{
    extern __shared__ float sm[];
    const uint32_t sbase = smem_u32(sm);
    const int tid  = threadIdx.x;
    const int warp = tid >> 5;
    const int lane = tid & 31;
    const int wm   = warp >> 1;         // 0..3
    const int wn   = warp & 1;          // 0..1
    const int m0   = blockIdx.y * 128;
    const int n0   = blockIdx.x * 128;
    const int nch  = K >> 5;
    const int segmask = (1 << seg_shift) - 1;

    const int lr = tid >> 1;            // loader row 0..127
    const int lh = tid & 1;             // loader half (16 floats each)

    auto issue = [&](int c) {
        const int kb  = c << 5;
        const int seg = kb >> seg_shift;
        const float* Asrc = (seg == 0) ? A0 : ((seg == 1) ? A1 : A2);
        const float* ap = Asrc + (((size_t)(m0 + lr)) << seg_shift) + (kb & segmask) + lh * 16;
        const float* bp = B + (size_t)(n0 + lr) * K + kb + lh * 16;
        const uint32_t abase = sbase + (c % STAGES) * STAGE_B + lr * (ROWPAD * 4) + lh * 64;
        const uint32_t bbase = abase + A_TILE_B;
#pragma unroll
        for (int j = 0; j < 4; j++) {
            cp16(abase + j * 16, ap + j * 4);
            cp16(bbase + j * 16, bp + j * 4);
        }
        asm volatile("cp.async.commit_group;" ::: "memory");
    };

    float acc[2][8][4];
#pragma unroll
    for (int mt = 0; mt < 2; mt++)
#pragma unroll
        for (int nt = 0; nt < 8; nt++)
#pragma unroll
            for (int r = 0; r < 4; r++) acc[mt][nt][r] = 0.0f;

    issue(0);
    issue(1);

    const int frow = lane >> 2;         // 0..7
    const int fcol = lane & 3;          // 0..3

    for (int c = 0; c < nch; c++) {
        asm volatile("cp.async.wait_group %0;" :: "n"(1) : "memory");
        __syncthreads();
        if (c + 2 < nch) issue(c + 2);
        else asm volatile("cp.async.commit_group;" ::: "memory");

        const float* sA = sm + (c % STAGES) * (STAGE_B / 4);
        const float* sB = sA + (A_TILE_B / 4);

#pragma unroll
        for (int ks = 0; ks < 4; ks++) {
            const int k0 = ks * 8 + fcol;
            uint32_t af[2][4], bf[8][2];
#pragma unroll
            for (int mt = 0; mt < 2; mt++) {
                const float* pa = sA + (wm * 32 + mt * 16 + frow) * ROWPAD + k0;
                af[mt][0] = __float_as_uint(pa[0]);
                af[mt][1] = __float_as_uint(pa[8 * ROWPAD]);
                af[mt][2] = __float_as_uint(pa[4]);
                af[mt][3] = __float_as_uint(pa[8 * ROWPAD + 4]);
            }
#pragma unroll
            for (int nt = 0; nt < 8; nt++) {
                const float* pb = sB + (wn * 64 + nt * 8 + frow) * ROWPAD + k0;
                bf[nt][0] = __float_as_uint(pb[0]);
                bf[nt][1] = __float_as_uint(pb[4]);
            }
#pragma unroll
            for (int mt = 0; mt < 2; mt++)
#pragma unroll
                for (int nt = 0; nt < 8; nt++)
                    mma_tf32(acc[mt][nt], af[mt], bf[nt]);
        }
        __syncthreads();
    }

    // ------------------------------ epilogue -------------------------------
#pragma unroll
    for (int mt = 0; mt < 2; mt++) {
        const int row = m0 + wm * 32 + mt * 16 + frow;
#pragma unroll
        for (int nt = 0; nt < 8; nt++) {
            const int col = n0 + wn * 64 + nt * 8 + fcol * 2;
            float b0 = 0.0f, b1 = 0.0f;
            if (bias != nullptr) { b0 = bias[col]; b1 = bias[col + 1]; }
            float2 v0, v1;
            v0.x = acc[mt][nt][0] * scale + b0;
            v0.y = acc[mt][nt][1] * scale + b1;
            v1.x = acc[mt][nt][2] * scale + b0;
            v1.y = acc[mt][nt][3] * scale + b1;
            if (round_out) {
                v0.x = tf32r(v0.x); v0.y = tf32r(v0.y);
                v1.x = tf32r(v1.x); v1.y = tf32r(v1.y);
            }
            *(float2*)(C + (size_t)row * Nfull + col)       = v0;
            *(float2*)(C + (size_t)(row + 8) * Nfull + col) = v1;
        }
    }
}

// ===========================================================================
// tf32 rounding copy (operand pre-conditioning)
// ===========================================================================
__global__ void __launch_bounds__(256)
round_kernel(float* __restrict__ dst, const float* __restrict__ src, int n4)
{
    int i = blockIdx.x * 256 + threadIdx.x;
    if (i < n4) {
        float4 x = ((const float4*)src)[i];
        x.x = tf32r(x.x); x.y = tf32r(x.y); x.z = tf32r(x.z); x.w = tf32r(x.w);
        ((float4*)dst)[i] = x;
    }
}

// v [8192,512] -> vT [512,8192]
__global__ void __launch_bounds__(256)
transpose_kernel(float* __restrict__ out, const float* __restrict__ in)
{
    __shared__ float tile[32][33];
    const int tx = threadIdx.x & 31;
    const int ty = threadIdx.x >> 5;
    const int x0 = blockIdx.x * 32;
    const int y0 = blockIdx.y * 32;
#pragma unroll
    for (int j = 0; j < 32; j += 8)
        tile[ty + j][tx] = in[(size_t)(y0 + ty + j) * CH + x0 + tx];
    __syncthreads();
#pragma unroll
    for (int j = 0; j < 32; j += 8)
        out[(size_t)(x0 + ty + j) * NROWS + y0 + tx] = tile[tx][ty + j];
}

// Row softmax over 8192 cols; output tf32-rounded (P feeds the next MMA)
__global__ void __launch_bounds__(256)
softmax_kernel(float* __restrict__ S)
{
    const int tid = threadIdx.x;
    float* p = S + (size_t)blockIdx.x * NROWS;
    __shared__ float red1[8];
    __shared__ float red2[8];

    float4 v[8];
#pragma unroll
    for (int i = 0; i < 8; i++)
        v[i] = *(const float4*)(p + (size_t)(i * 256 + tid) * 4);

    float m = -3.0e38f;
#pragma unroll
    for (int i = 0; i < 8; i++)
        m = fmaxf(m, fmaxf(fmaxf(v[i].x, v[i].y), fmaxf(v[i].z, v[i].w)));
#pragma unroll
    for (int o = 16; o > 0; o >>= 1)
        m = fmaxf(m, __shfl_xor_sync(0xffffffff, m, o));
    if ((tid & 31) == 0) red1[tid >> 5] = m;
    __syncthreads();
    m = red1[0];
#pragma unroll
    for (int i = 1; i < 8; i++) m = fmaxf(m, red1[i]);

    float s = 0.0f;
#pragma unroll
    for (int i = 0; i < 8; i++) {
        v[i].x = __expf(v[i].x - m); s += v[i].x;
        v[i].y = __expf(v[i].y - m); s += v[i].y;
        v[i].z = __expf(v[i].z - m); s += v[i].z;
        v[i].w = __expf(v[i].w - m); s += v[i].w;
    }
#pragma unroll
    for (int o = 16; o > 0; o >>= 1)
        s += __shfl_xor_sync(0xffffffff, s, o);
    if ((tid & 31) == 0) red2[tid >> 5] = s;
    __syncthreads();
    s = 0.0f;
#pragma unroll
    for (int i = 0; i < 8; i++) s += red2[i];
    const float inv = 1.0f / s;

#pragma unroll
    for (int i = 0; i < 8; i++) {
        v[i].x = tf32r(v[i].x * inv); v[i].y = tf32r(v[i].y * inv);
        v[i].z = tf32r(v[i].z * inv); v[i].w = tf32r(v[i].w * inv);
        *(float4*)(p + (size_t)(i * 256 + tid) * 4) = v[i];
    }
}

__global__ void __launch_bounds__(256)
gate_kernel(float* __restrict__ g, const float* __restrict__ a1,
            const float* __restrict__ a2, int n)
{
    int i = blockIdx.x * 256 + threadIdx.x;
    if (i < n) {
        float s1 = 1.0f / (1.0f + __expf(-a1[i]));
        float s2 = 1.0f / (1.0f + __expf(-a2[i]));
        g[i] = 1.0f / (1.0f + __expf(-(s1 - s2)));
    }
}

__global__ void __launch_bounds__(256)
combine_kernel(float* __restrict__ out, const float* __restrict__ g,
               const float* __restrict__ A1, const float* __restrict__ A2, int n)
{
    int i = blockIdx.x * 256 + threadIdx.x;
    if (i < n) {
        float gg = g[i];
        out[i] = gg * A1[i] + (1.0f - gg) * A2[i];
    }
}

// ===========================================================================
extern "C" void kernel_launch(void* const* d_in, const int* in_sizes, int n_in,
                              void* d_out, int out_size)
{
    const float* sp   = (const float*)d_in[0];
    const float* om1  = (const float*)d_in[1];
    const float* om2  = (const float*)d_in[2];
    const float* q_w  = (const float*)d_in[3];
    const float* q_b  = (const float*)d_in[4];
    const float* k1_w = (const float*)d_in[5];
    const float* k1_b = (const float*)d_in[6];
    const float* k2_w = (const float*)d_in[7];
    const float* k2_b = (const float*)d_in[8];
    const float* v_w  = (const float*)d_in[9];
    const float* v_b  = (const float*)d_in[10];
    const float* c1_w = (const float*)d_in[11];
    const float* c1_b = (const float*)d_in[12];
    float* out = (float*)d_out;

    float* base = nullptr;
    cudaGetSymbolAddress((void**)&base, g_scratch);
    float* q     = base + 0 * NC;
    float* k1    = base + 1 * NC;
    float* k2    = base + 2 * NC;
    float* v     = base + 3 * NC;
    float* a1    = base + 4 * NC;   // reused as vT after gate
    float* a2    = base + 5 * NC;
    float* gate  = base + 6 * NC;
    float* attn1 = base + 7 * NC;
    float* attn2 = base + 8 * NC;
    float* spr   = base + 9 * NC;
    float* om1r  = base + 10 * NC;
    float* om2r  = base + 11 * NC;
    float* S     = base + 12 * NC;
    float* wts   = base + 12 * NC + S_ELEMS;
    float* qwr   = wts;
    float* k1wr  = wts + 262144;
    float* k2wr  = wts + 524288;
    float* vwr   = wts + 786432;            // 512*1536
    float* c1wr  = wts + 1572864;           // 512*1024
    float* vT    = a1;

    cudaFuncSetAttribute(mma_nt_kernel,
                         cudaFuncAttributeMaxDynamicSharedMemorySize, SMEM_GEMM);

    const float scale = 0.044194173824159223f;  // 1/sqrt(512)
    const int elemBlocks = (int)((NC + 255) / 256);

    auto gemm = [&](float* C, const float* A0, const float* A1p, const float* A2p,
                    const float* B, const float* bias, int M, int Nfull, int K,
                    int seg_shift, float sc, int round_out) {
        dim3 g(Nfull / 128, M / 128);
        mma_nt_kernel<<<g, 256, SMEM_GEMM>>>(C, A0, A1p, A2p, B, bias,
                                             Nfull, K, seg_shift, sc, round_out);
    };

    // --- operand pre-rounding (tf32 rna) ---
    round_kernel<<<(int)(NC / 4 + 255) / 256, 256>>>(spr,  sp,  (int)(NC / 4));
    round_kernel<<<(int)(NC / 4 + 255) / 256, 256>>>(om1r, om1, (int)(NC / 4));
    round_kernel<<<(int)(NC / 4 + 255) / 256, 256>>>(om2r, om2, (int)(NC / 4));
    round_kernel<<<(262144 / 4 + 255) / 256, 256>>>(qwr,  q_w,  262144 / 4);
    round_kernel<<<(262144 / 4 + 255) / 256, 256>>>(k1wr, k1_w, 262144 / 4);
    round_kernel<<<(262144 / 4 + 255) / 256, 256>>>(k2wr, k2_w, 262144 / 4);
    round_kernel<<<(786432 / 4 + 255) / 256, 256>>>(vwr,  v_w,  786432 / 4);
    round_kernel<<<(524288 / 4 + 255) / 256, 256>>>(c1wr, c1_w, 524288 / 4);

    // --- projections (outputs rounded: they feed further MMAs) ---
    gemm(q,  spr,  nullptr, nullptr, qwr,  q_b,  NROWS, CH, 512, 9, 1.0f, 1);
    gemm(k1, om1r, nullptr, nullptr, k1wr, k1_b, NROWS, CH, 512, 9, 1.0f, 1);
    gemm(k2, om2r, nullptr, nullptr, k2wr, k2_b, NROWS, CH, 512, 9, 1.0f, 1);
    gemm(v,  spr,  om1r, om2r, vwr, v_b, NROWS, CH, 1536, 9, 1.0f, 1);

    // --- gate ---
    gemm(a1, spr, om1r, nullptr, c1wr, c1_b, NROWS, CH, 1024, 9, 1.0f, 0);
    gemm(a2, spr, om2r, nullptr, c1wr, c1_b, NROWS, CH, 1024, 9, 1.0f, 0);
    gate_kernel<<<elemBlocks, 256>>>(gate, a1, a2, (int)NC);

    // --- V transpose (vT overwrites a1 slot; gate already computed) ---
    transpose_kernel<<<dim3(CH / 32, NROWS / 32), 256>>>(vT, v);

    // --- attention 1 ---
    gemm(S, q, nullptr, nullptr, k1, nullptr, NROWS, NROWS, 512, 9, scale, 0);
    softmax_kernel<<<NROWS, 256>>>(S);
    gemm(attn1, S, nullptr, nullptr, vT, nullptr, NROWS, CH, NROWS, 13, 1.0f, 0);

    // --- attention 2 ---
    gemm(S, q, nullptr, nullptr, k2, nullptr, NROWS, NROWS, 512, 9, scale, 0);
    softmax_kernel<<<NROWS, 256>>>(S);
    gemm(attn2, S, nullptr, nullptr, vT, nullptr, NROWS, CH, NROWS, 13, 1.0f, 0);

    // --- combine ---
    combine_kernel<<<elemBlocks, 256>>>(out, gate, attn1, attn2, (int)NC);
}

// round 4
// speedup vs baseline: 4.6132x; 2.4124x over previous
#include <cuda_runtime.h>
#include <cuda_fp16.h>
#include <cstdint>

#define NROWS 8192
#define CH    512
#define NC    ((size_t)NROWS * CH)          // 4,194,304
#define S_ELEMS ((size_t)NROWS * NROWS)     // 67,108,864

// float区: a1,a2,gate,attn1,attn2 (5*NC), S (S_ELEMS)
// half区 : sph,om1h,om2h,qh,k1h,k2h,vh,vTh (8*NC), P (S_ELEMS), weights (2,097,152)
#define FLOAT_REGION (5 * NC + S_ELEMS)
#define HALF_REGION  (8 * NC + S_ELEMS + 2097152)
__device__ float g_scratch[FLOAT_REGION + HALF_REGION / 2 + 1024];

// ===========================================================================
// helpers
// ===========================================================================
__device__ __forceinline__ uint32_t smem_u32(const void* p) {
    uint32_t a;
    asm("{ .reg .u64 t; cvta.to.shared.u64 t, %1; cvt.u32.u64 %0, t; }"
        : "=r"(a) : "l"(p));
    return a;
}
__device__ __forceinline__ void cp16(uint32_t dst, const void* src) {
    asm volatile("cp.async.cg.shared.global [%0], [%1], 16;" :: "r"(dst), "l"(src));
}
__device__ __forceinline__ void ldmx4(uint32_t* r, uint32_t addr) {
    asm volatile("ldmatrix.sync.aligned.m8n8.x4.shared.b16 {%0,%1,%2,%3}, [%4];"
                 : "=r"(r[0]), "=r"(r[1]), "=r"(r[2]), "=r"(r[3]) : "r"(addr));
}
__device__ __forceinline__ void mma_f16(float* d, const uint32_t* a,
                                        uint32_t b0, uint32_t b1) {
    asm volatile(
        "mma.sync.aligned.m16n8k16.row.col.f32.f16.f16.f32 "
        "{%0,%1,%2,%3}, {%4,%5,%6,%7}, {%8,%9}, {%0,%1,%2,%3};"
        : "+f"(d[0]), "+f"(d[1]), "+f"(d[2]), "+f"(d[3])
        : "r"(a[0]), "r"(a[1]), "r"(a[2]), "r"(a[3]), "r"(b0), "r"(b1));
}
// 16B-chunk swizzle within a 64B row (rows interleave bank halves by r&1;
// even/odd row groups rotate chunk slot by (r>>1)&3) -> ldmatrix conflict-free
__device__ __forceinline__ uint32_t sw16(int r, int c) {
    return (uint32_t)((c ^ ((r >> 1) & 3)) * 16);
}

// ===========================================================================
// fp16 NT GEMM via mma.sync.m16n8k16: C[M x Nfull] = scale*(A @ B^T) + bias
//   A: fp16 K-major, optionally 3-segment K-concat (seg len = 1<<seg_shift)
//   B: fp16 [Nfull, K] row-major
// 256 threads = 8 warps (4m x 2n), per-warp 32x64, BK=32, 4-stage cp.async.
// ===========================================================================
#define STAGES   4
#define A_TILE_B 8192                  // 128 rows * 64B
#define STAGE_B  16384
#define SMEM_GEMM (STAGES * STAGE_B)   // 65536

template <typename OutT>
__global__ void __launch_bounds__(256, 2)
mma_nt_kernel(OutT* __restrict__ C,
              const __half* __restrict__ A0, const __half* __restrict__ A1,
              const __half* __restrict__ A2,
              const __half* __restrict__ B, const float* __restrict__ bias,
              int Nfull, int K, int seg_shift, float scale)
{
    extern __shared__ char sm[];
    const uint32_t sbase = smem_u32(sm);
    const int tid  = threadIdx.x;
    const int warp = tid >> 5;
    const int lane = tid & 31;
    const int wm   = warp >> 1;          // 0..3
    const int wn   = warp & 1;           // 0..1
    const int m0   = blockIdx.y * 128;
    const int n0   = blockIdx.x * 128;
    const int nch  = K >> 5;
    const int segmask = (1 << seg_shift) - 1;

    const int lr = tid >> 1;             // loader row 0..127
    const int lc0 = (tid & 1) * 2;       // first of 2 chunks

    auto issue = [&](int c) {
        const int kb  = c << 5;
        const int seg = kb >> seg_shift;
        const __half* Asrc = (seg == 0) ? A0 : ((seg == 1) ? A1 : A2);
        const __half* ap = Asrc + (((size_t)(m0 + lr)) << seg_shift) + (kb & segmask);
        const __half* bp = B + (size_t)(n0 + lr) * K + kb;
        const uint32_t st = sbase + (c % STAGES) * STAGE_B + lr * 64;
#pragma unroll
        for (int j = 0; j < 2; j++) {
            const int ch = lc0 + j;
            cp16(st + sw16(lr, ch), ap + ch * 8);
            cp16(st + A_TILE_B + sw16(lr, ch), bp + ch * 8);
        }
        asm volatile("cp.async.commit_group;" ::: "memory");
    };

    float acc[2][8][4];
#pragma unroll
    for (int mt = 0; mt < 2; mt++)
#pragma unroll
        for (int nt = 0; nt < 8; nt++)
#pragma unroll
            for (int r = 0; r < 4; r++) acc[mt][nt][r] = 0.0f;

    issue(0); issue(1); issue(2);

    const int l15 = lane & 15;
    const int lhi = lane >> 4;
    // fragment smem offsets (within stage)
    uint32_t aoff[2][2], boff[4][2];
#pragma unroll
    for (int mt = 0; mt < 2; mt++)
#pragma unroll
        for (int ks = 0; ks < 2; ks++) {
            const int r = wm * 32 + mt * 16 + l15;
            aoff[mt][ks] = (uint32_t)r * 64 + sw16(r, 2 * ks + lhi);
        }
#pragma unroll
    for (int np = 0; np < 4; np++)
#pragma unroll
        for (int ks = 0; ks < 2; ks++) {
            const int r = wn * 64 + np * 16 + l15;
            boff[np][ks] = A_TILE_B + (uint32_t)r * 64 + sw16(r, 2 * ks + lhi);
        }

    for (int c = 0; c < nch; c++) {
        asm volatile("cp.async.wait_group %0;" :: "n"(2) : "memory");
        __syncthreads();
        if (c + 3 < nch) issue(c + 3);
        else asm volatile("cp.async.commit_group;" ::: "memory");

        const uint32_t st = sbase + (c % STAGES) * STAGE_B;
#pragma unroll
        for (int ks = 0; ks < 2; ks++) {
            uint32_t af[2][4], bf[4][4];
            ldmx4(af[0], st + aoff[0][ks]);
            ldmx4(af[1], st + aoff[1][ks]);
#pragma unroll
            for (int np = 0; np < 4; np++) ldmx4(bf[np], st + boff[np][ks]);
#pragma unroll
            for (int mt = 0; mt < 2; mt++)
#pragma unroll
                for (int np = 0; np < 4; np++) {
                    mma_f16(acc[mt][2 * np],     af[mt], bf[np][0], bf[np][2]);
                    mma_f16(acc[mt][2 * np + 1], af[mt], bf[np][1], bf[np][3]);
                }
        }
    }

    // ------------------------------ epilogue -------------------------------
    const int frow = lane >> 2;
    const int fcol = lane & 3;
#pragma unroll
    for (int mt = 0; mt < 2; mt++) {
        const int row = m0 + wm * 32 + mt * 16 + frow;
#pragma unroll
        for (int nt = 0; nt < 8; nt++) {
            const int col = n0 + wn * 64 + nt * 8 + fcol * 2;
            float b0 = 0.0f, b1 = 0.0f;
            if (bias != nullptr) { b0 = bias[col]; b1 = bias[col + 1]; }
            float x0 = acc[mt][nt][0] * scale + b0;
            float x1 = acc[mt][nt][1] * scale + b1;
            float x2 = acc[mt][nt][2] * scale + b0;
            float x3 = acc[mt][nt][3] * scale + b1;
            if constexpr (sizeof(OutT) == 2) {
                *(__half2*)((__half*)C + (size_t)row * Nfull + col) =
                    __floats2half2_rn(x0, x1);
                *(__half2*)((__half*)C + (size_t)(row + 8) * Nfull + col) =
                    __floats2half2_rn(x2, x3);
            } else {
                *(float2*)((float*)C + (size_t)row * Nfull + col) = make_float2(x0, x1);
                *(float2*)((float*)C + (size_t)(row + 8) * Nfull + col) = make_float2(x2, x3);
            }
        }
    }
}

// ===========================================================================
__global__ void __launch_bounds__(256)
f2h_kernel(__half* __restrict__ dst, const float* __restrict__ src, int n4)
{
    int i = blockIdx.x * 256 + threadIdx.x;
    if (i < n4) {
        float4 x = ((const float4*)src)[i];
        ((__half2*)dst)[2 * i]     = __floats2half2_rn(x.x, x.y);
        ((__half2*)dst)[2 * i + 1] = __floats2half2_rn(x.z, x.w);
    }
}

// v fp16 [8192,512] -> vT fp16 [512,8192]
__global__ void __launch_bounds__(256)
transpose_h_kernel(__half* __restrict__ out, const __half* __restrict__ in)
{
    __shared__ __half tile[32][34];
    const int tx = threadIdx.x & 31;
    const int ty = threadIdx.x >> 5;
    const int x0 = blockIdx.x * 32;
    const int y0 = blockIdx.y * 32;
#pragma unroll
    for (int j = 0; j < 32; j += 8)
        tile[ty + j][tx] = in[(size_t)(y0 + ty + j) * CH + x0 + tx];
    __syncthreads();
#pragma unroll
    for (int j = 0; j < 32; j += 8)
        out[(size_t)(x0 + ty + j) * NROWS + y0 + tx] = tile[tx][ty + j];
}

// Row softmax: reads fp32 S row (8192), writes fp16 P row
__global__ void __launch_bounds__(256)
softmax_kernel(const float* __restrict__ S, __half* __restrict__ P)
{
    const int tid = threadIdx.x;
    const float* p = S + (size_t)blockIdx.x * NROWS;
    __half* po = P + (size_t)blockIdx.x * NROWS;
    __shared__ float red1[8];
    __shared__ float red2[8];

    float4 v[8];
#pragma unroll
    for (int i = 0; i < 8; i++)
        v[i] = *(const float4*)(p + (size_t)(i * 256 + tid) * 4);

    float m = -3.0e38f;
#pragma unroll
    for (int i = 0; i < 8; i++)
        m = fmaxf(m, fmaxf(fmaxf(v[i].x, v[i].y), fmaxf(v[i].z, v[i].w)));
#pragma unroll
    for (int o = 16; o > 0; o >>= 1)
        m = fmaxf(m, __shfl_xor_sync(0xffffffff, m, o));
    if ((tid & 31) == 0) red1[tid >> 5] = m;
    __syncthreads();
    m = red1[0];
#pragma unroll
    for (int i = 1; i < 8; i++) m = fmaxf(m, red1[i]);

    float s = 0.0f;
#pragma unroll
    for (int i = 0; i < 8; i++) {
        v[i].x = __expf(v[i].x - m); s += v[i].x;
        v[i].y = __expf(v[i].y - m); s += v[i].y;
        v[i].z = __expf(v[i].z - m); s += v[i].z;
        v[i].w = __expf(v[i].w - m); s += v[i].w;
    }
#pragma unroll
    for (int o = 16; o > 0; o >>= 1)
        s += __shfl_xor_sync(0xffffffff, s, o);
    if ((tid & 31) == 0) red2[tid >> 5] = s;
    __syncthreads();
    s = 0.0f;
#pragma unroll
    for (int i = 0; i < 8; i++) s += red2[i];
    const float inv = 1.0f / s;

#pragma unroll
    for (int i = 0; i < 8; i++) {
        const size_t pos = (size_t)(i * 256 + tid) * 4;
        *(__half2*)(po + pos)     = __floats2half2_rn(v[i].x * inv, v[i].y * inv);
        *(__half2*)(po + pos + 2) = __floats2half2_rn(v[i].z * inv, v[i].w * inv);
    }
}

__global__ void __launch_bounds__(256)
gate_kernel(float* __restrict__ g, const float* __restrict__ a1,
            const float* __restrict__ a2, int n)
{
    int i = blockIdx.x * 256 + threadIdx.x;
    if (i < n) {
        float s1 = 1.0f / (1.0f + __expf(-a1[i]));
        float s2 = 1.0f / (1.0f + __expf(-a2[i]));
        g[i] = 1.0f / (1.0f + __expf(-(s1 - s2)));
    }
}

__global__ void __launch_bounds__(256)
combine_kernel(float* __restrict__ out, const float* __restrict__ g,
               const float* __restrict__ A1, const float* __restrict__ A2, int n)
{
    int i = blockIdx.x * 256 + threadIdx.x;
    if (i < n) {
        float gg = g[i];
        out[i] = gg * A1[i] + (1.0f - gg) * A2[i];
    }
}

// ===========================================================================
extern "C" void kernel_launch(void* const* d_in, const int* in_sizes, int n_in,
                              void* d_out, int out_size)
{
    const float* sp   = (const float*)d_in[0];
    const float* om1  = (const float*)d_in[1];
    const float* om2  = (const float*)d_in[2];
    const float* q_w  = (const float*)d_in[3];
    const float* q_b  = (const float*)d_in[4];
    const float* k1_w = (const float*)d_in[5];
    const float* k1_b = (const float*)d_in[6];
    const float* k2_w = (const float*)d_in[7];
    const float* k2_b = (const float*)d_in[8];
    const float* v_w  = (const float*)d_in[9];
    const float* v_b  = (const float*)d_in[10];
    const float* c1_w = (const float*)d_in[11];
    const float* c1_b = (const float*)d_in[12];
    float* out = (float*)d_out;

    float* base = nullptr;
    cudaGetSymbolAddress((void**)&base, g_scratch);
    float* a1    = base + 0 * NC;
    float* a2    = base + 1 * NC;
    float* gate  = base + 2 * NC;
    float* attn1 = base + 3 * NC;
    float* attn2 = base + 4 * NC;
    float* S     = base + 5 * NC;
    __half* hb   = (__half*)(base + FLOAT_REGION);
    __half* sph  = hb + 0 * NC;
    __half* om1h = hb + 1 * NC;
    __half* om2h = hb + 2 * NC;
    __half* qh   = hb + 3 * NC;
    __half* k1h  = hb + 4 * NC;
    __half* k2h  = hb + 5 * NC;
    __half* vh   = hb + 6 * NC;
    __half* vTh  = hb + 7 * NC;
    __half* P    = hb + 8 * NC;
    __half* wts  = P + S_ELEMS;
    __half* qwh  = wts;
    __half* k1wh = wts + 262144;
    __half* k2wh = wts + 524288;
    __half* vwh  = wts + 786432;          // 512*1536
    __half* c1wh = wts + 1572864;         // 512*1024

    cudaFuncSetAttribute(mma_nt_kernel<float>,
                         cudaFuncAttributeMaxDynamicSharedMemorySize, SMEM_GEMM);
    cudaFuncSetAttribute(mma_nt_kernel<__half>,
                         cudaFuncAttributeMaxDynamicSharedMemorySize, SMEM_GEMM);

    const float scale = 0.044194173824159223f;  // 1/sqrt(512)
    const int elemBlocks = (int)((NC + 255) / 256);

    auto gemm_h = [&](__half* C, const __half* A0, const __half* A1p, const __half* A2p,
                      const __half* B, const float* bias, int M, int Nfull, int K,
                      int seg_shift, float sc) {
        dim3 g(Nfull / 128, M / 128);
        mma_nt_kernel<__half><<<g, 256, SMEM_GEMM>>>(C, A0, A1p, A2p, B, bias,
                                                     Nfull, K, seg_shift, sc);
    };
    auto gemm_f = [&](float* C, const __half* A0, const __half* A1p, const __half* A2p,
                      const __half* B, const float* bias, int M, int Nfull, int K,
                      int seg_shift, float sc) {
        dim3 g(Nfull / 128, M / 128);
        mma_nt_kernel<float><<<g, 256, SMEM_GEMM>>>(C, A0, A1p, A2p, B, bias,
                                                    Nfull, K, seg_shift, sc);
    };

    // --- fp32 -> fp16 operand conversion ---
    f2h_kernel<<<(int)(NC / 4 + 255) / 256, 256>>>(sph,  sp,  (int)(NC / 4));
    f2h_kernel<<<(int)(NC / 4 + 255) / 256, 256>>>(om1h, om1, (int)(NC / 4));
    f2h_kernel<<<(int)(NC / 4 + 255) / 256, 256>>>(om2h, om2, (int)(NC / 4));
    f2h_kernel<<<(262144 / 4 + 255) / 256, 256>>>(qwh,  q_w,  262144 / 4);
    f2h_kernel<<<(262144 / 4 + 255) / 256, 256>>>(k1wh, k1_w, 262144 / 4);
    f2h_kernel<<<(262144 / 4 + 255) / 256, 256>>>(k2wh, k2_w, 262144 / 4);
    f2h_kernel<<<(786432 / 4 + 255) / 256, 256>>>(vwh,  v_w,  786432 / 4);
    f2h_kernel<<<(524288 / 4 + 255) / 256, 256>>>(c1wh, c1_w, 524288 / 4);

    // --- projections (fp16 outputs feed further MMAs) ---
    gemm_h(qh,  sph,  nullptr, nullptr, qwh,  q_b,  NROWS, CH, 512, 9, 1.0f);
    gemm_h(k1h, om1h, nullptr, nullptr, k1wh, k1_b, NROWS, CH, 512, 9, 1.0f);
    gemm_h(k2h, om2h, nullptr, nullptr, k2wh, k2_b, NROWS, CH, 512, 9, 1.0f);
    gemm_h(vh,  sph,  om1h, om2h, vwh, v_b, NROWS, CH, 1536, 9, 1.0f);

    // --- gate ---
    gemm_f(a1, sph, om1h, nullptr, c1wh, c1_b, NROWS, CH, 1024, 9, 1.0f);
    gemm_f(a2, sph, om2h, nullptr, c1wh, c1_b, NROWS, CH, 1024, 9, 1.0f);
    gate_kernel<<<elemBlocks, 256>>>(gate, a1, a2, (int)NC);

    // --- V transpose ---
    transpose_h_kernel<<<dim3(CH / 32, NROWS / 32), 256>>>(vTh, vh);

    // --- attention 1 ---
    gemm_f(S, qh, nullptr, nullptr, k1h, nullptr, NROWS, NROWS, 512, 9, scale);
    softmax_kernel<<<NROWS, 256>>>(S, P);
    gemm_f(attn1, P, nullptr, nullptr, vTh, nullptr, NROWS, CH, NROWS, 13, 1.0f);

    // --- attention 2 ---
    gemm_f(S, qh, nullptr, nullptr, k2h, nullptr, NROWS, NROWS, 512, 9, scale);
    softmax_kernel<<<NROWS, 256>>>(S, P);
    gemm_f(attn2, P, nullptr, nullptr, vTh, nullptr, NROWS, CH, NROWS, 13, 1.0f);

    // --- combine ---
    combine_kernel<<<elemBlocks, 256>>>(out, gate, attn1, attn2, (int)NC);
}

// round 5
// speedup vs baseline: 4.6839x; 1.0153x over previous
#include <cuda_runtime.h>
#include <cuda_fp16.h>
#include <cstdint>

#define NROWS 8192
#define CH    512
#define NC    ((size_t)NROWS * CH)          // 4,194,304
#define S_ELEMS ((size_t)NROWS * NROWS)     // 67,108,864

// float region: a1,a2,gate,attn1,attn2 (5*NC), S (S_ELEMS)
// half  region: sph,om1h,om2h,qh,k1h,k2h,vh,vTh (8*NC), P (S_ELEMS), weights
#define FLOAT_REGION (5 * NC + S_ELEMS)
#define HALF_REGION  (8 * NC + S_ELEMS + 2097152)
__device__ float g_scratch[FLOAT_REGION + HALF_REGION / 2 + 1024];

// ===========================================================================
// helpers
// ===========================================================================
__device__ __forceinline__ uint32_t smem_u32(const void* p) {
    uint32_t a;
    asm("{ .reg .u64 t; cvta.to.shared.u64 t, %1; cvt.u32.u64 %0, t; }"
        : "=r"(a) : "l"(p));
    return a;
}
__device__ __forceinline__ void cp16(uint32_t dst, const void* src) {
    asm volatile("cp.async.cg.shared.global [%0], [%1], 16;" :: "r"(dst), "l"(src));
}
__device__ __forceinline__ void ldmx4(uint32_t* r, uint32_t addr) {
    asm volatile("ldmatrix.sync.aligned.m8n8.x4.shared.b16 {%0,%1,%2,%3}, [%4];"
                 : "=r"(r[0]), "=r"(r[1]), "=r"(r[2]), "=r"(r[3]) : "r"(addr));
}
__device__ __forceinline__ void mma_f16(float* d, const uint32_t* a,
                                        uint32_t b0, uint32_t b1) {
    asm volatile(
        "mma.sync.aligned.m16n8k16.row.col.f32.f16.f16.f32 "
        "{%0,%1,%2,%3}, {%4,%5,%6,%7}, {%8,%9}, {%0,%1,%2,%3};"
        : "+f"(d[0]), "+f"(d[1]), "+f"(d[2]), "+f"(d[3])
        : "r"(a[0]), "r"(a[1]), "r"(a[2]), "r"(a[3]), "r"(b0), "r"(b1));
}
// 16B-chunk swizzle within a 64B row -> conflict-free ldmatrix + cp.async
__device__ __forceinline__ uint32_t sw16(int r, int c) {
    return (uint32_t)((c ^ ((r >> 1) & 3)) * 16);
}

// ===========================================================================
// fp16 NT GEMM via mma.sync.m16n8k16: C[M x Nfull] = scale*(A @ B^T) + bias
//   A: fp16 K-major, optionally 3-segment K-concat (seg len = 1<<seg_shift)
//   B: fp16 [Nfull, K] row-major
// 256 threads = 8 warps (4m x 2n), per-warp 32x64, BK=32, 4-stage cp.async.
// ===========================================================================
#define STAGES   4
#define A_TILE_B 8192                  // 128 rows * 64B
#define STAGE_B  16384
#define SMEM_GEMM (STAGES * STAGE_B)   // 65536

template <typename OutT>
__global__ void __launch_bounds__(256, 2)
mma_nt_kernel(OutT* __restrict__ C,
              const __half* __restrict__ A0, const __half* __restrict__ A1,
              const __half* __restrict__ A2,
              const __half* __restrict__ B, const float* __restrict__ bias,
              int Nfull, int K, int seg_shift, float scale)
{
    extern __shared__ char sm[];
    const uint32_t sbase = smem_u32(sm);
    const int tid  = threadIdx.x;
    const int warp = tid >> 5;
    const int lane = tid & 31;
    const int wm   = warp >> 1;          // 0..3
    const int wn   = warp & 1;           // 0..1
    const int m0   = blockIdx.y * 128;
    const int n0   = blockIdx.x * 128;
    const int nch  = K >> 5;
    const int segmask = (1 << seg_shift) - 1;

    const int lr = tid >> 1;             // loader row 0..127
    const int lc0 = (tid & 1) * 2;       // first of 2 chunks

    auto issue = [&](int c) {
        const int kb  = c << 5;
        const int seg = kb >> seg_shift;
        const __half* Asrc = (seg == 0) ? A0 : ((seg == 1) ? A1 : A2);
        const __half* ap = Asrc + (((size_t)(m0 + lr)) << seg_shift) + (kb & segmask);
        const __half* bp = B + (size_t)(n0 + lr) * K + kb;
        const uint32_t st = sbase + (c % STAGES) * STAGE_B + lr * 64;
#pragma unroll
        for (int j = 0; j < 2; j++) {
            const int ch = lc0 + j;
            cp16(st + sw16(lr, ch), ap + ch * 8);
            cp16(st + A_TILE_B + sw16(lr, ch), bp + ch * 8);
        }
        asm volatile("cp.async.commit_group;" ::: "memory");
    };

    float acc[2][8][4];
#pragma unroll
    for (int mt = 0; mt < 2; mt++)
#pragma unroll
        for (int nt = 0; nt < 8; nt++)
#pragma unroll
            for (int r = 0; r < 4; r++) acc[mt][nt][r] = 0.0f;

    issue(0); issue(1); issue(2);

    const int l15 = lane & 15;
    const int lhi = lane >> 4;
    uint32_t aoff[2][2], boff[4][2];
#pragma unroll
    for (int mt = 0; mt < 2; mt++)
#pragma unroll
        for (int ks = 0; ks < 2; ks++) {
            const int r = wm * 32 + mt * 16 + l15;
            aoff[mt][ks] = (uint32_t)r * 64 + sw16(r, 2 * ks + lhi);
        }
#pragma unroll
    for (int np = 0; np < 4; np++)
#pragma unroll
        for (int ks = 0; ks < 2; ks++) {
            const int r = wn * 64 + np * 16 + l15;
            boff[np][ks] = A_TILE_B + (uint32_t)r * 64 + sw16(r, 2 * ks + lhi);
        }

    for (int c = 0; c < nch; c++) {
        asm volatile("cp.async.wait_group %0;" :: "n"(2) : "memory");
        __syncthreads();
        if (c + 3 < nch) issue(c + 3);
        else asm volatile("cp.async.commit_group;" ::: "memory");

        const uint32_t st = sbase + (c % STAGES) * STAGE_B;

        // ks = 0: load A frags for ks=0 AND ks=1 (prefetch), B for ks=0
        uint32_t af0[2][4], af1[2][4], bf[4][4];
        ldmx4(af0[0], st + aoff[0][0]);
        ldmx4(af0[1], st + aoff[1][0]);
        ldmx4(af1[0], st + aoff[0][1]);
        ldmx4(af1[1], st + aoff[1][1]);
#pragma unroll
        for (int np = 0; np < 4; np++) ldmx4(bf[np], st + boff[np][0]);
#pragma unroll
        for (int mt = 0; mt < 2; mt++)
#pragma unroll
            for (int np = 0; np < 4; np++) {
                mma_f16(acc[mt][2 * np],     af0[mt], bf[np][0], bf[np][2]);
                mma_f16(acc[mt][2 * np + 1], af0[mt], bf[np][1], bf[np][3]);
            }
        // ks = 1: B frags loaded here, A already in registers
#pragma unroll
        for (int np = 0; np < 4; np++) ldmx4(bf[np], st + boff[np][1]);
#pragma unroll
        for (int mt = 0; mt < 2; mt++)
#pragma unroll
            for (int np = 0; np < 4; np++) {
                mma_f16(acc[mt][2 * np],     af1[mt], bf[np][0], bf[np][2]);
                mma_f16(acc[mt][2 * np + 1], af1[mt], bf[np][1], bf[np][3]);
            }
    }

    // ------------------------------ epilogue -------------------------------
    const int frow = lane >> 2;
    const int fcol = lane & 3;
#pragma unroll
    for (int mt = 0; mt < 2; mt++) {
        const int row = m0 + wm * 32 + mt * 16 + frow;
#pragma unroll
        for (int nt = 0; nt < 8; nt++) {
            const int col = n0 + wn * 64 + nt * 8 + fcol * 2;
            float b0 = 0.0f, b1 = 0.0f;
            if (bias != nullptr) { b0 = bias[col]; b1 = bias[col + 1]; }
            float x0 = acc[mt][nt][0] * scale + b0;
            float x1 = acc[mt][nt][1] * scale + b1;
            float x2 = acc[mt][nt][2] * scale + b0;
            float x3 = acc[mt][nt][3] * scale + b1;
            if constexpr (sizeof(OutT) == 2) {
                *(__half2*)((__half*)C + (size_t)row * Nfull + col) =
                    __floats2half2_rn(x0, x1);
                *(__half2*)((__half*)C + (size_t)(row + 8) * Nfull + col) =
                    __floats2half2_rn(x2, x3);
            } else {
                *(float2*)((float*)C + (size_t)row * Nfull + col) = make_float2(x0, x1);
                *(float2*)((float*)C + (size_t)(row + 8) * Nfull + col) = make_float2(x2, x3);
            }
        }
    }
}

// ===========================================================================
// One fused fp32->fp16 conversion kernel for all 8 operands (segment table).
// Segment sizes in float4 units.
// ===========================================================================
#define SEG_IN  ((int)(NC / 4))          // 1,048,576 each for sp/om1/om2
#define SEG_W5  65536                    // q_w,k1_w,k2_w (512x512 / 4)
#define SEG_VW  196608                   // v_w (512*1536/4)
#define SEG_CW  131072                   // c1_w (512*1024/4)
#define CVT_TOTAL (3 * SEG_IN + 3 * SEG_W5 + SEG_VW + SEG_CW)  // 3,670,016

__global__ void __launch_bounds__(256)
convert_all_kernel(const float* __restrict__ sp, const float* __restrict__ om1,
                   const float* __restrict__ om2, const float* __restrict__ qw,
                   const float* __restrict__ k1w, const float* __restrict__ k2w,
                   const float* __restrict__ vw, const float* __restrict__ cw,
                   __half* __restrict__ sph, __half* __restrict__ om1h,
                   __half* __restrict__ om2h, __half* __restrict__ qwh,
                   __half* __restrict__ k1wh, __half* __restrict__ k2wh,
                   __half* __restrict__ vwh, __half* __restrict__ cwh)
{
    int i = blockIdx.x * 256 + threadIdx.x;
    if (i >= CVT_TOTAL) return;
    const float* src; __half* dst; int off = i;
    if (off < SEG_IN) { src = sp; dst = sph; }
    else if ((off -= SEG_IN) < SEG_IN) { src = om1; dst = om1h; }
    else if ((off -= SEG_IN) < SEG_IN) { src = om2; dst = om2h; }
    else if ((off -= SEG_IN) < SEG_W5) { src = qw; dst = qwh; }
    else if ((off -= SEG_W5) < SEG_W5) { src = k1w; dst = k1wh; }
    else if ((off -= SEG_W5) < SEG_W5) { src = k2w; dst = k2wh; }
    else if ((off -= SEG_W5) < SEG_VW) { src = vw; dst = vwh; }
    else { off -= SEG_VW; src = cw; dst = cwh; }
    float4 x = ((const float4*)src)[off];
    ((__half2*)dst)[2 * off]     = __floats2half2_rn(x.x, x.y);
    ((__half2*)dst)[2 * off + 1] = __floats2half2_rn(x.z, x.w);
}

// v fp16 [8192,512] -> vT fp16 [512,8192]
__global__ void __launch_bounds__(256)
transpose_h_kernel(__half* __restrict__ out, const __half* __restrict__ in)
{
    __shared__ __half tile[32][34];
    const int tx = threadIdx.x & 31;
    const int ty = threadIdx.x >> 5;
    const int x0 = blockIdx.x * 32;
    const int y0 = blockIdx.y * 32;
#pragma unroll
    for (int j = 0; j < 32; j += 8)
        tile[ty + j][tx] = in[(size_t)(y0 + ty + j) * CH + x0 + tx];
    __syncthreads();
#pragma unroll
    for (int j = 0; j < 32; j += 8)
        out[(size_t)(x0 + ty + j) * NROWS + y0 + tx] = tile[tx][ty + j];
}

// Row softmax: reads fp32 S row (8192), writes fp16 P row
__global__ void __launch_bounds__(256)
softmax_kernel(const float* __restrict__ S, __half* __restrict__ P)
{
    const int tid = threadIdx.x;
    const float* p = S + (size_t)blockIdx.x * NROWS;
    __half* po = P + (size_t)blockIdx.x * NROWS;
    __shared__ float red1[8];
    __shared__ float red2[8];

    float4 v[8];
#pragma unroll
    for (int i = 0; i < 8; i++)
        v[i] = *(const float4*)(p + (size_t)(i * 256 + tid) * 4);

    float m = -3.0e38f;
#pragma unroll
    for (int i = 0; i < 8; i++)
        m = fmaxf(m, fmaxf(fmaxf(v[i].x, v[i].y), fmaxf(v[i].z, v[i].w)));
#pragma unroll
    for (int o = 16; o > 0; o >>= 1)
        m = fmaxf(m, __shfl_xor_sync(0xffffffff, m, o));
    if ((tid & 31) == 0) red1[tid >> 5] = m;
    __syncthreads();
    m = red1[0];
#pragma unroll
    for (int i = 1; i < 8; i++) m = fmaxf(m, red1[i]);

    float s = 0.0f;
#pragma unroll
    for (int i = 0; i < 8; i++) {
        v[i].x = __expf(v[i].x - m); s += v[i].x;
        v[i].y = __expf(v[i].y - m); s += v[i].y;
        v[i].z = __expf(v[i].z - m); s += v[i].z;
        v[i].w = __expf(v[i].w - m); s += v[i].w;
    }
#pragma unroll
    for (int o = 16; o > 0; o >>= 1)
        s += __shfl_xor_sync(0xffffffff, s, o);
    if ((tid & 31) == 0) red2[tid >> 5] = s;
    __syncthreads();
    s = 0.0f;
#pragma unroll
    for (int i = 0; i < 8; i++) s += red2[i];
    const float inv = 1.0f / s;

#pragma unroll
    for (int i = 0; i < 8; i++) {
        const size_t pos = (size_t)(i * 256 + tid) * 4;
        *(__half2*)(po + pos)     = __floats2half2_rn(v[i].x * inv, v[i].y * inv);
        *(__half2*)(po + pos + 2) = __floats2half2_rn(v[i].z * inv, v[i].w * inv);
    }
}

__global__ void __launch_bounds__(256)
gate_kernel(float* __restrict__ g, const float* __restrict__ a1,
            const float* __restrict__ a2, int n)
{
    int i = blockIdx.x * 256 + threadIdx.x;
    if (i < n) {
        float s1 = 1.0f / (1.0f + __expf(-a1[i]));
        float s2 = 1.0f / (1.0f + __expf(-a2[i]));
        g[i] = 1.0f / (1.0f + __expf(-(s1 - s2)));
    }
}

__global__ void __launch_bounds__(256)
combine_kernel(float* __restrict__ out, const float* __restrict__ g,
               const float* __restrict__ A1, const float* __restrict__ A2, int n)
{
    int i = blockIdx.x * 256 + threadIdx.x;
    if (i < n) {
        float gg = g[i];
        out[i] = gg * A1[i] + (1.0f - gg) * A2[i];
    }
}

// ===========================================================================
extern "C" void kernel_launch(void* const* d_in, const int* in_sizes, int n_in,
                              void* d_out, int out_size)
{
    const float* sp   = (const float*)d_in[0];
    const float* om1  = (const float*)d_in[1];
    const float* om2  = (const float*)d_in[2];
    const float* q_w  = (const float*)d_in[3];
    const float* q_b  = (const float*)d_in[4];
    const float* k1_w = (const float*)d_in[5];
    const float* k1_b = (const float*)d_in[6];
    const float* k2_w = (const float*)d_in[7];
    const float* k2_b = (const float*)d_in[8];
    const float* v_w  = (const float*)d_in[9];
    const float* v_b  = (const float*)d_in[10];
    const float* c1_w = (const float*)d_in[11];
    const float* c1_b = (const float*)d_in[12];
    float* out = (float*)d_out;

    float* base = nullptr;
    cudaGetSymbolAddress((void**)&base, g_scratch);
    float* a1    = base + 0 * NC;
    float* a2    = base + 1 * NC;
    float* gate  = base + 2 * NC;
    float* attn1 = base + 3 * NC;
    float* attn2 = base + 4 * NC;
    float* S     = base + 5 * NC;
    __half* hb   = (__half*)(base + FLOAT_REGION);
    __half* sph  = hb + 0 * NC;
    __half* om1h = hb + 1 * NC;
    __half* om2h = hb + 2 * NC;
    __half* qh   = hb + 3 * NC;
    __half* k1h  = hb + 4 * NC;
    __half* k2h  = hb + 5 * NC;
    __half* vh   = hb + 6 * NC;
    __half* vTh  = hb + 7 * NC;
    __half* P    = hb + 8 * NC;
    __half* wts  = P + S_ELEMS;
    __half* qwh  = wts;
    __half* k1wh = wts + 262144;
    __half* k2wh = wts + 524288;
    __half* vwh  = wts + 786432;
    __half* c1wh = wts + 1572864;

    cudaFuncSetAttribute(mma_nt_kernel<float>,
                         cudaFuncAttributeMaxDynamicSharedMemorySize, SMEM_GEMM);
    cudaFuncSetAttribute(mma_nt_kernel<__half>,
                         cudaFuncAttributeMaxDynamicSharedMemorySize, SMEM_GEMM);

    const float scale = 0.044194173824159223f;  // 1/sqrt(512)
    const int elemBlocks = (int)((NC + 255) / 256);

    auto gemm_h = [&](__half* C, const __half* A0, const __half* A1p, const __half* A2p,
                      const __half* B, const float* bias, int M, int Nfull, int K,
                      int seg_shift, float sc) {
        dim3 g(Nfull / 128, M / 128);
        mma_nt_kernel<__half><<<g, 256, SMEM_GEMM>>>(C, A0, A1p, A2p, B, bias,
                                                     Nfull, K, seg_shift, sc);
    };
    auto gemm_f = [&](float* C, const __half* A0, const __half* A1p, const __half* A2p,
                      const __half* B, const float* bias, int M, int Nfull, int K,
                      int seg_shift, float sc) {
        dim3 g(Nfull / 128, M / 128);
        mma_nt_kernel<float><<<g, 256, SMEM_GEMM>>>(C, A0, A1p, A2p, B, bias,
                                                    Nfull, K, seg_shift, sc);
    };

    // (1) fused operand conversion
    convert_all_kernel<<<(CVT_TOTAL + 255) / 256, 256>>>(
        sp, om1, om2, q_w, k1_w, k2_w, v_w, c1_w,
        sph, om1h, om2h, qwh, k1wh, k2wh, vwh, c1wh);

    // (2-5) projections
    gemm_h(qh,  sph,  nullptr, nullptr, qwh,  q_b,  NROWS, CH, 512, 9, 1.0f);
    gemm_h(k1h, om1h, nullptr, nullptr, k1wh, k1_b, NROWS, CH, 512, 9, 1.0f);
    gemm_h(k2h, om2h, nullptr, nullptr, k2wh, k2_b, NROWS, CH, 512, 9, 1.0f);
    gemm_h(vh,  sph,  om1h, om2h, vwh, v_b, NROWS, CH, 1536, 9, 1.0f);

    // (6) S1 = q k1^T   <-- ncu -s 5 -c 1 profiles THIS launch
    gemm_f(S, qh, nullptr, nullptr, k1h, nullptr, NROWS, NROWS, 512, 9, scale);
    // (7) softmax1 -> P
    softmax_kernel<<<NROWS, 256>>>(S, P);
    // (8) V transpose
    transpose_h_kernel<<<dim3(CH / 32, NROWS / 32), 256>>>(vTh, vh);
    // (9) attn1 = P vT^T
    gemm_f(attn1, P, nullptr, nullptr, vTh, nullptr, NROWS, CH, NROWS, 13, 1.0f);

    // (10-12) gates
    gemm_f(a1, sph, om1h, nullptr, c1wh, c1_b, NROWS, CH, 1024, 9, 1.0f);
    gemm_f(a2, sph, om2h, nullptr, c1wh, c1_b, NROWS, CH, 1024, 9, 1.0f);
    gate_kernel<<<elemBlocks, 256>>>(gate, a1, a2, (int)NC);

    // (13-15) attention 2
    gemm_f(S, qh, nullptr, nullptr, k2h, nullptr, NROWS, NROWS, 512, 9, scale);
    softmax_kernel<<<NROWS, 256>>>(S, P);
    gemm_f(attn2, P, nullptr, nullptr, vTh, nullptr, NROWS, CH, NROWS, 13, 1.0f);

    // (16) combine
    combine_kernel<<<elemBlocks, 256>>>(out, gate, attn1, attn2, (int)NC);
}